// round 10
// baseline (speedup 1.0000x reference)
#include <cuda_runtime.h>
#include <cstdint>

// OMul: r[i] = outer(x[i], y[i]) flattened.
// x: [N, 256] f32, y: [N, 256] f32, out: [N, 65536] f32.
// Pure HBM-write-bound: 1 GiB of .cs streaming stores.
//
// R10: champion R9 (grid=4096, 1 row/CTA, smem-staged inputs, warp-uniform
// LDS broadcast, full unroll) combined with 256-bit streaming stores
// (st.global.cs.v8.b32): 32 straight-line STG.256 per thread, 1KB
// contiguous per warp per store, minimum store-path instruction count.
//
// Layout: warp w (0..7), lane l (0..31). Iteration i (0..31): m = w + 8*i
// (warp-uniform), thread writes out[row*65536 + m*256 + l*8 .. +7].

static constexpr int M = 256;
static constexpr int K = 256;
static constexpr int THREADS = 256;

__device__ __forceinline__ void stg_cs_v8(float* ptr,
                                          float a0, float a1, float a2, float a3,
                                          float a4, float a5, float a6, float a7)
{
    asm volatile(
        "st.global.cs.v8.b32 [%0], {%1, %2, %3, %4, %5, %6, %7, %8};"
        :: "l"(ptr),
           "r"(__float_as_uint(a0)), "r"(__float_as_uint(a1)),
           "r"(__float_as_uint(a2)), "r"(__float_as_uint(a3)),
           "r"(__float_as_uint(a4)), "r"(__float_as_uint(a5)),
           "r"(__float_as_uint(a6)), "r"(__float_as_uint(a7))
        : "memory");
}

__global__ __launch_bounds__(THREADS, 8)
void omul_kernel(const float* __restrict__ x,
                 const float* __restrict__ y,
                 float* __restrict__ out)
{
    __shared__ float sx[M];
    __shared__ float sy[K];

    const int row = blockIdx.x;
    const int t   = threadIdx.x;

    sx[t] = x[(size_t)row * M + t];
    sy[t] = y[(size_t)row * K + t];
    __syncthreads();

    const int w = t >> 5;         // warp id (0..7)
    const int l = t & 31;         // lane

    // Thread owns k chunk [l*8, l*8+8).
    const float4 ya = reinterpret_cast<const float4*>(sy)[l * 2 + 0];
    const float4 yb = reinterpret_cast<const float4*>(sy)[l * 2 + 1];

    float* orow = out + (size_t)row * (M * K) + (size_t)w * K + l * 8;

    #pragma unroll
    for (int i = 0; i < 32; i++) {
        const float xv = sx[w + i * 8];   // warp-uniform smem broadcast
        stg_cs_v8(orow + (size_t)i * (8 * K),
                  xv * ya.x, xv * ya.y, xv * ya.z, xv * ya.w,
                  xv * yb.x, xv * yb.y, xv * yb.z, xv * yb.w);
    }
}

extern "C" void kernel_launch(void* const* d_in, const int* in_sizes, int n_in,
                              void* d_out, int out_size)
{
    const float* x = (const float*)d_in[0];
    const float* y = (const float*)d_in[1];
    float* out = (float*)d_out;

    const int n = in_sizes[0] / M;   // 4096 rows

    omul_kernel<<<n, THREADS>>>(x, y, out);
}

// round 11
// speedup vs baseline: 1.0327x; 1.0327x over previous
#include <cuda_runtime.h>

// OMul: r[i] = outer(x[i], y[i]) flattened.
// x: [N, 256] f32, y: [N, 256] f32, out: [N, 65536] f32.
// Pure HBM-write-bound: 1 GiB of .cs streaming stores.
//
// R11: R9 champion (grid=4096, 1 row/CTA, smem-staged, full unroll,
// __stcs float4 stores) with contiguous per-thread m-blocks so x reads
// become vectorized: 16 LDS.128 per thread instead of 64 LDS.32, cutting
// LSU ops/thread 128 -> 80 on the shared LSU dispatch path.
//
// Layout: k4 = t & 63 (float4 k-chunk), m0 = t >> 6 (m block 0..3).
// Thread sweeps m = m0*64 + mi, mi = 0..63. Per warp per iteration:
// 32 lanes x 16B = 512B contiguous (half a 1KB k-row), warp-uniform xv.

static constexpr int M = 256;
static constexpr int K = 256;
static constexpr int THREADS = 256;

__global__ __launch_bounds__(THREADS, 8)
void omul_kernel(const float* __restrict__ x,
                 const float* __restrict__ y,
                 float* __restrict__ out)
{
    __shared__ float sx[M];
    __shared__ float sy[K];

    const int row = blockIdx.x;
    const int t   = threadIdx.x;

    sx[t] = x[(size_t)row * M + t];
    sy[t] = y[(size_t)row * K + t];
    __syncthreads();

    const int k4 = t & 63;        // which float4 chunk of k (0..63)
    const int m0 = t >> 6;        // m block (0..3): m in [m0*64, m0*64+64)

    const float4 y4 = reinterpret_cast<const float4*>(sy)[k4];

    float4* out4 = reinterpret_cast<float4*>(
        out + (size_t)row * (M * K) + (size_t)m0 * 64 * K);

    const float4* sx4 = reinterpret_cast<const float4*>(sx) + m0 * 16;

    #pragma unroll
    for (int g = 0; g < 16; g++) {
        const float4 xg = sx4[g];           // LDS.128, warp-uniform broadcast
        #pragma unroll
        for (int j = 0; j < 4; j++) {
            const float xv = j == 0 ? xg.x : j == 1 ? xg.y : j == 2 ? xg.z : xg.w;
            const int m = g * 4 + j;        // local m within block (0..63)
            float4 v;
            v.x = xv * y4.x;
            v.y = xv * y4.y;
            v.z = xv * y4.z;
            v.w = xv * y4.w;
            // streaming store: output never re-read, full 128B sector coverage
            __stcs(&out4[(size_t)m * 64 + k4], v);
        }
    }
}

extern "C" void kernel_launch(void* const* d_in, const int* in_sizes, int n_in,
                              void* d_out, int out_size)
{
    const float* x = (const float*)d_in[0];
    const float* y = (const float*)d_in[1];
    float* out = (float*)d_out;

    const int n = in_sizes[0] / M;   // 4096 rows

    omul_kernel<<<n, THREADS>>>(x, y, out);
}